// round 17
// baseline (speedup 1.0000x reference)
#include <cuda_runtime.h>
#include <cuda_bf16.h>
#include <cuda_fp8.h>
#include <cstdint>

#define BATCH  8
#define DMODEL 512
#define QBEF   4096
#define QAFT   1024
#define NKEYS  4096

#define N_QKV  (BATCH * QBEF * DMODEL)
#define N_QDS  (BATCH * QAFT * DMODEL)
#define N_S    ((long long)BATCH * QAFT * NKEYS)
#define N_WD   (QAFT * QBEF)
#define N_W    (DMODEL * DMODEL)

#define RSCALE 1024.0f
#define RINV   9.765625e-4f

// ---------------------------------------------------------------------------
// Scratch triples: h = bf16 hi, q = e4m3(hi), r = e4m3((x-hi)*1024)
// ---------------------------------------------------------------------------
__device__ __align__(16) __nv_bfloat16 g_qTh[N_QKV]; __device__ __align__(16) unsigned char g_qTq[N_QKV], g_qTr[N_QKV];
__device__ __align__(16) __nv_bfloat16 g_knh[N_QKV]; __device__ __align__(16) unsigned char g_knq[N_QKV], g_knr[N_QKV];
__device__ __align__(16) __nv_bfloat16 g_vnh[N_QKV]; __device__ __align__(16) unsigned char g_vnq[N_QKV], g_vnr[N_QKV];
__device__ __align__(16) __nv_bfloat16 g_wdh[N_WD];  __device__ __align__(16) unsigned char g_wdq[N_WD],  g_wdr[N_WD];
__device__ __align__(16) __nv_bfloat16 g_wqh[N_W];   __device__ __align__(16) unsigned char g_wqq[N_W],   g_wqr[N_W];
__device__ __align__(16) __nv_bfloat16 g_wkh[N_W];   __device__ __align__(16) unsigned char g_wkq[N_W],   g_wkr[N_W];
__device__ __align__(16) __nv_bfloat16 g_wvh[N_W];   __device__ __align__(16) unsigned char g_wvq[N_W],   g_wvr[N_W];
__device__ __align__(16) __nv_bfloat16 g_woh[N_W];   __device__ __align__(16) unsigned char g_woq[N_W],   g_wor[N_W];
__device__ __align__(16) __nv_bfloat16 g_dsh[N_QDS]; __device__ __align__(16) unsigned char g_dsq[N_QDS], g_dsr[N_QDS];
__device__ __align__(16) __nv_bfloat16 g_qh[N_QDS];  __device__ __align__(16) unsigned char g_qq[N_QDS],  g_qr[N_QDS];
__device__ __align__(16) __nv_bfloat16 g_kh[N_QKV];  __device__ __align__(16) unsigned char g_kq[N_QKV],  g_kr[N_QKV];
__device__ __align__(16) __nv_bfloat16 g_vth[N_QKV]; __device__ __align__(16) unsigned char g_vtq[N_QKV], g_vtr[N_QKV];
__device__ __align__(16) __nv_bfloat16 g_ph[N_S];    __device__ __align__(16) unsigned char g_pq[N_S],    g_pr[N_S];
__device__ __align__(16) __nv_bfloat16 g_ath[N_QDS]; __device__ __align__(16) unsigned char g_atq[N_QDS], g_atr[N_QDS];
__device__ __align__(16) float g_s[N_S];

// ---------------------------------------------------------------------------
// PTX helpers
// ---------------------------------------------------------------------------
__device__ __forceinline__ void cpasync16(uint32_t dst, const void* src) {
    asm volatile("cp.async.cg.shared.global [%0], [%1], 16;\n" :: "r"(dst), "l"(src));
}
__device__ __forceinline__ void cp_commit() { asm volatile("cp.async.commit_group;\n"); }
__device__ __forceinline__ void cp_wait1()  { asm volatile("cp.async.wait_group 1;\n" ::: "memory"); }
__device__ __forceinline__ void cp_wait0()  { asm volatile("cp.async.wait_group 0;\n" ::: "memory"); }

__device__ __forceinline__ void ldsm4(uint32_t* r, uint32_t a) {
    asm volatile("ldmatrix.sync.aligned.m8n8.x4.shared.b16 {%0,%1,%2,%3}, [%4];"
        : "=r"(r[0]), "=r"(r[1]), "=r"(r[2]), "=r"(r[3]) : "r"(a));
}
__device__ __forceinline__ void mma_bf16(float* c, const uint32_t* a, const uint32_t* b) {
    asm volatile(
        "mma.sync.aligned.m16n8k16.row.col.f32.bf16.bf16.f32 "
        "{%0,%1,%2,%3}, {%4,%5,%6,%7}, {%8,%9}, {%0,%1,%2,%3};"
        : "+f"(c[0]), "+f"(c[1]), "+f"(c[2]), "+f"(c[3])
        : "r"(a[0]), "r"(a[1]), "r"(a[2]), "r"(a[3]), "r"(b[0]), "r"(b[1]));
}
__device__ __forceinline__ void mma_fp8(float* c, const uint32_t* a, const uint32_t* b) {
    asm volatile(
        "mma.sync.aligned.m16n8k32.row.col.f32.e4m3.e4m3.f32 "
        "{%0,%1,%2,%3}, {%4,%5,%6,%7}, {%8,%9}, {%0,%1,%2,%3};"
        : "+f"(c[0]), "+f"(c[1]), "+f"(c[2]), "+f"(c[3])
        : "r"(a[0]), "r"(a[1]), "r"(a[2]), "r"(a[3]), "r"(b[0]), "r"(b[1]));
}

__device__ __forceinline__ unsigned char to_fp8(float x) {
    return (unsigned char)__nv_cvt_float_to_fp8(x, __NV_SATFINITE, __NV_E4M3);
}

// ---------------------------------------------------------------------------
// Hybrid GEMM: D = scale*(A@B^T) (+biasM)(+biasN); A,B NT (both [rows,K]).
// Main term bf16 (m16n8k16), corrections e4m3 (m16n8k32), residuals x1024.
// Tile 128x64, BK=32, 256 thr = 8 warps (4m x 2n), warp 32x32, 2-stage.
// CMODE: 0 = fp32 out (+mask), 1 = triple out, 2 = triple out TRANSPOSED.
// Stage layout (all row strides 16B-aligned):
//   Ah@0     128x80B = 10240
//   Bh@10240  64x80B =  5120
//   Aq@15360 128x48B =  6144
//   Ar@21504 128x48B =  6144
//   Bq@27648  64x48B =  3072
//   Br@30720  64x48B =  3072   -> STAGEB 33792
// ---------------------------------------------------------------------------
#define STAGEB 33792u
#define SMEM_G (2 * STAGEB)

template <int CMODE>
__global__ __launch_bounds__(256, 2)
void gemm_h(const __nv_bfloat16* __restrict__ Ahg, const unsigned char* __restrict__ Aqg,
            const unsigned char* __restrict__ Arg,
            const __nv_bfloat16* __restrict__ Bhg, const unsigned char* __restrict__ Bqg,
            const unsigned char* __restrict__ Brg,
            float* __restrict__ Cf, __nv_bfloat16* __restrict__ Ch,
            unsigned char* __restrict__ Cq, unsigned char* __restrict__ Cr,
            int M, int N, int K,
            long long sA, long long sB, long long sC,
            const float* __restrict__ biasN, const float* __restrict__ biasM,
            float scale, const int* __restrict__ mask, long long sMask, int tRows)
{
    extern __shared__ __align__(16) char smem_buf[];
    const int tid  = threadIdx.x;
    const int lane = tid & 31;
    const int warp = tid >> 5;
    const int warpM = warp >> 1;
    const int warpN = warp & 1;
    const int bz = blockIdx.z;
    const int rowBase = blockIdx.y * 128;
    const int colBase = blockIdx.x * 64;

    const __nv_bfloat16* Ah = Ahg + bz * sA;
    const unsigned char* Aq = Aqg + bz * sA;
    const unsigned char* Ar = Arg + bz * sA;
    const __nv_bfloat16* Bh = Bhg + bz * sB;
    const unsigned char* Bq = Bqg + bz * sB;
    const unsigned char* Br = Brg + bz * sB;

    const uint32_t smb = (uint32_t)__cvta_generic_to_shared(smem_buf);

    auto load_stage = [&](int kt, int s) {
        const uint32_t base = smb + s * STAGEB;
        {   // Ah bf16: 128 rows x 64B, stride 80B (512 chunks)
#pragma unroll
            for (int i = 0; i < 2; i++) {
                int idx = tid + i * 256;
                int row = idx >> 2, c = (idx & 3) * 16;     // byte col
                cpasync16(base + (uint32_t)(row * 80 + c),
                          Ah + (size_t)(rowBase + row) * K + kt * 32 + (c >> 1));
            }
        }
        {   // Bh bf16: 64 rows x 64B (256 chunks)
            int n = tid >> 2, c = (tid & 3) * 16;
            cpasync16(base + 10240 + (uint32_t)(n * 80 + c),
                      Bh + (size_t)(colBase + n) * K + kt * 32 + (c >> 1));
        }
        {   // Aq/Ar fp8: 128 rows x 32B, stride 48B (256 chunks each)
            int row = tid >> 1, c = (tid & 1) * 16;
            size_t go = (size_t)(rowBase + row) * K + kt * 32 + c;
            cpasync16(base + 15360 + (uint32_t)(row * 48 + c), Aq + go);
            cpasync16(base + 21504 + (uint32_t)(row * 48 + c), Ar + go);
        }
        if (tid < 128) {   // Bq/Br fp8: 64 rows x 32B, stride 48B (128 chunks each)
            int n = tid >> 1, c = (tid & 1) * 16;
            size_t go = (size_t)(colBase + n) * K + kt * 32 + c;
            cpasync16(base + 27648 + (uint32_t)(n * 48 + c), Bq + go);
            cpasync16(base + 30720 + (uint32_t)(n * 48 + c), Br + go);
        }
    };

    // ldmatrix address components (all 16B-aligned)
    const int arow = warpM * 32 + (lane & 15);
    const uint32_t aoff  = (uint32_t)(arow * 80 + (lane >> 4) * 16);
    const uint32_t a8off = (uint32_t)(arow * 48 + (lane >> 4) * 16);
    const int bn = warpN * 32 + (lane & 7) + ((lane >> 4) << 3);
    const uint32_t boff  = (uint32_t)(bn * 80 + ((lane >> 3) & 1) * 16);
    const uint32_t b8off = (uint32_t)(bn * 48 + ((lane >> 3) & 1) * 16);

    float accM[2][4][4], accC[2][4][4];
#pragma unroll
    for (int mt = 0; mt < 2; mt++)
#pragma unroll
        for (int nt = 0; nt < 4; nt++)
#pragma unroll
            for (int i = 0; i < 4; i++) { accM[mt][nt][i] = 0.0f; accC[mt][nt][i] = 0.0f; }

    const int nkt = K / 32;
    load_stage(0, 0); cp_commit();

    for (int kt = 0; kt < nkt; kt++) {
        const bool more = (kt + 1 < nkt);
        if (more) { load_stage(kt + 1, (kt + 1) & 1); cp_commit(); cp_wait1(); }
        else      { cp_wait0(); }
        __syncthreads();

        const uint32_t sb = smb + (kt & 1) * STAGEB;

        // ---- fp8 corrections: full k32 per instruction ----
        {
            uint32_t aq8[2][4], ar8[2][4], bq8[2][4], br8[2][4];
#pragma unroll
            for (int mt = 0; mt < 2; mt++) {
                ldsm4(aq8[mt], sb + 15360 + a8off + mt * 768);
                ldsm4(ar8[mt], sb + 21504 + a8off + mt * 768);
            }
#pragma unroll
            for (int g = 0; g < 2; g++) {
                ldsm4(bq8[g], sb + 27648 + b8off + g * 768);
                ldsm4(br8[g], sb + 30720 + b8off + g * 768);
            }
#pragma unroll
            for (int mt = 0; mt < 2; mt++)
#pragma unroll
                for (int nt = 0; nt < 4; nt++) {
                    const int g = nt >> 1, hf = (nt & 1) * 2;
                    uint32_t bQ[2] = { bq8[g][hf], bq8[g][hf + 1] };
                    uint32_t bR[2] = { br8[g][hf], br8[g][hf + 1] };
                    mma_fp8(accC[mt][nt], ar8[mt], bQ);   // (Al*1024)*Bh
                    mma_fp8(accC[mt][nt], aq8[mt], bR);   // Ah*(Bl*1024)
                }
        }

        // ---- bf16 main term ----
#pragma unroll
        for (int kk = 0; kk < 2; kk++) {
            uint32_t ah[2][4], bh[2][4];
#pragma unroll
            for (int mt = 0; mt < 2; mt++)
                ldsm4(ah[mt], sb + aoff + (uint32_t)(mt * 1280 + kk * 32));
#pragma unroll
            for (int g = 0; g < 2; g++)
                ldsm4(bh[g], sb + 10240 + boff + (uint32_t)(g * 1280 + kk * 32));
#pragma unroll
            for (int mt = 0; mt < 2; mt++)
#pragma unroll
                for (int nt = 0; nt < 4; nt++) {
                    const int g = nt >> 1, hf = (nt & 1) * 2;
                    uint32_t bH[2] = { bh[g][hf], bh[g][hf + 1] };
                    mma_bf16(accM[mt][nt], ah[mt], bH);
                }
        }
        __syncthreads();
    }

    // ---- epilogue ----
    const int g = lane >> 2, t = lane & 3;
    float* CfB = Cf ? (Cf + (long long)bz * sC) : nullptr;
    __nv_bfloat16* ChB = Ch ? (Ch + (long long)bz * sC) : nullptr;
    unsigned char* CqB = Cq ? (Cq + (long long)bz * sC) : nullptr;
    unsigned char* CrB = Cr ? (Cr + (long long)bz * sC) : nullptr;
    const int* maskB = mask ? (mask + (long long)bz * sMask) : nullptr;

#pragma unroll
    for (int mt = 0; mt < 2; mt++) {
#pragma unroll
        for (int nt = 0; nt < 4; nt++) {
            const int r0 = rowBase + warpM * 32 + mt * 16 + g;
            const int r1 = r0 + 8;
            const int cc = colBase + warpN * 32 + nt * 8 + 2 * t;
            float v[4];
#pragma unroll
            for (int i = 0; i < 4; i++)
                v[i] = (accM[mt][nt][i] + accC[mt][nt][i] * RINV) * scale;
            if (biasM) { float b0 = biasM[r0], b1 = biasM[r1]; v[0] += b0; v[1] += b0; v[2] += b1; v[3] += b1; }
            if (biasN) { float b0 = biasN[cc], b1 = biasN[cc + 1]; v[0] += b0; v[1] += b1; v[2] += b0; v[3] += b1; }
            if (CMODE == 0) {
                if (maskB) {
                    const float NINF = __int_as_float(0xff800000);
                    if (maskB[(long long)r0 * N + cc])     v[0] = NINF;
                    if (maskB[(long long)r0 * N + cc + 1]) v[1] = NINF;
                    if (maskB[(long long)r1 * N + cc])     v[2] = NINF;
                    if (maskB[(long long)r1 * N + cc + 1]) v[3] = NINF;
                }
                *(float2*)(CfB + (long long)r0 * N + cc) = make_float2(v[0], v[1]);
                *(float2*)(CfB + (long long)r1 * N + cc) = make_float2(v[2], v[3]);
            } else if (CMODE == 1) {
                __nv_bfloat16 h[4]; unsigned short qp[2], rp[2];
#pragma unroll
                for (int i = 0; i < 4; i++) h[i] = __float2bfloat16_rn(v[i]);
                qp[0] = (unsigned short)to_fp8(__bfloat162float(h[0])) | ((unsigned short)to_fp8(__bfloat162float(h[1])) << 8);
                qp[1] = (unsigned short)to_fp8(__bfloat162float(h[2])) | ((unsigned short)to_fp8(__bfloat162float(h[3])) << 8);
                rp[0] = (unsigned short)to_fp8((v[0] - __bfloat162float(h[0])) * RSCALE) |
                        ((unsigned short)to_fp8((v[1] - __bfloat162float(h[1])) * RSCALE) << 8);
                rp[1] = (unsigned short)to_fp8((v[2] - __bfloat162float(h[2])) * RSCALE) |
                        ((unsigned short)to_fp8((v[3] - __bfloat162float(h[3])) * RSCALE) << 8);
                __nv_bfloat162 H0; H0.x = h[0]; H0.y = h[1];
                __nv_bfloat162 H1; H1.x = h[2]; H1.y = h[3];
                *(__nv_bfloat162*)(ChB + (long long)r0 * N + cc) = H0;
                *(__nv_bfloat162*)(ChB + (long long)r1 * N + cc) = H1;
                *(unsigned short*)(CqB + (long long)r0 * N + cc) = qp[0];
                *(unsigned short*)(CqB + (long long)r1 * N + cc) = qp[1];
                *(unsigned short*)(CrB + (long long)r0 * N + cc) = rp[0];
                *(unsigned short*)(CrB + (long long)r1 * N + cc) = rp[1];
            } else {   // transposed triple
                const int rr[4] = { r0, r0, r1, r1 };
                const int nn[4] = { cc, cc + 1, cc, cc + 1 };
#pragma unroll
                for (int i = 0; i < 4; i++) {
                    __nv_bfloat16 h = __float2bfloat16_rn(v[i]);
                    long long o = (long long)nn[i] * tRows + rr[i];
                    ChB[o] = h;
                    CqB[o] = to_fp8(__bfloat162float(h));
                    CrB[o] = to_fp8((v[i] - __bfloat162float(h)) * RSCALE);
                }
            }
        }
    }
}

// ---------------------------------------------------------------------------
// triple split helpers
// ---------------------------------------------------------------------------
__device__ __forceinline__ void split4t(const float* src, __nv_bfloat16* h,
                                        unsigned char* q, unsigned char* r, long long i)
{
    float4 v = *(const float4*)(src + i);
    float vv[4] = { v.x, v.y, v.z, v.w };
    __nv_bfloat16 hh[4]; unsigned char qq[4], rr[4];
#pragma unroll
    for (int j = 0; j < 4; j++) {
        hh[j] = __float2bfloat16_rn(vv[j]);
        float hf = __bfloat162float(hh[j]);
        qq[j] = to_fp8(hf);
        rr[j] = to_fp8((vv[j] - hf) * RSCALE);
    }
    __nv_bfloat162 H0; H0.x = hh[0]; H0.y = hh[1];
    __nv_bfloat162 H1; H1.x = hh[2]; H1.y = hh[3];
    *(__nv_bfloat162*)(h + i) = H0; *(__nv_bfloat162*)(h + i + 2) = H1;
    *(uint32_t*)(q + i) = (uint32_t)qq[0] | ((uint32_t)qq[1] << 8) | ((uint32_t)qq[2] << 16) | ((uint32_t)qq[3] << 24);
    *(uint32_t*)(r + i) = (uint32_t)rr[0] | ((uint32_t)rr[1] << 8) | ((uint32_t)rr[2] << 16) | ((uint32_t)rr[3] << 24);
}

__global__ __launch_bounds__(256)
void split2_kernel(const float* __restrict__ s0, const float* __restrict__ s1,
                   __nv_bfloat16* __restrict__ h0, unsigned char* __restrict__ q0, unsigned char* __restrict__ r0,
                   __nv_bfloat16* __restrict__ h1, unsigned char* __restrict__ q1, unsigned char* __restrict__ r1)
{
    long long i = ((long long)blockIdx.x * 256 + threadIdx.x) * 4;
    if (i >= N_QKV) return;
    if (blockIdx.y == 0) split4t(s0, h0, q0, r0, i);
    else                 split4t(s1, h1, q1, r1, i);
}

__global__ __launch_bounds__(256)
void splitW_kernel(const float* __restrict__ wd, const float* __restrict__ wq,
                   const float* __restrict__ wk, const float* __restrict__ wv,
                   const float* __restrict__ wo,
                   __nv_bfloat16* wdh, unsigned char* wdq, unsigned char* wdr,
                   __nv_bfloat16* wqh, unsigned char* wqq, unsigned char* wqr,
                   __nv_bfloat16* wkh, unsigned char* wkq, unsigned char* wkr,
                   __nv_bfloat16* wvh, unsigned char* wvq, unsigned char* wvr,
                   __nv_bfloat16* woh, unsigned char* woq, unsigned char* wor)
{
    long long i = ((long long)blockIdx.x * 256 + threadIdx.x) * 4;
    const int y = blockIdx.y;
    const long long n = (y == 0) ? (long long)N_WD : (long long)N_W;
    if (i >= n) return;
    const float* s = (y == 0) ? wd : (y == 1) ? wq : (y == 2) ? wk : (y == 3) ? wv : wo;
    __nv_bfloat16* h = (y == 0) ? wdh : (y == 1) ? wqh : (y == 2) ? wkh : (y == 3) ? wvh : woh;
    unsigned char* q = (y == 0) ? wdq : (y == 1) ? wqq : (y == 2) ? wkq : (y == 3) ? wvq : woq;
    unsigned char* r = (y == 0) ? wdr : (y == 1) ? wqr : (y == 2) ? wkr : (y == 3) ? wvr : wor;
    split4t(s, h, q, r, i);
}

// queries transpose + triple split: [b,qb,d] -> [b,d,qb]
__global__ __launch_bounds__(256)
void tsplit_kernel(const float* __restrict__ src,
                   __nv_bfloat16* __restrict__ th, unsigned char* __restrict__ tq,
                   unsigned char* __restrict__ tr)
{
    __shared__ float tile[32][33];
    const int b = blockIdx.z;
    const int qb0 = blockIdx.x * 32, d0 = blockIdx.y * 32;
    const int tx = threadIdx.x & 31, ty = threadIdx.x >> 5;
    const float* sb = src + (size_t)b * QBEF * DMODEL;
#pragma unroll
    for (int i = 0; i < 4; i++)
        tile[ty + i * 8][tx] = sb[(size_t)(qb0 + ty + i * 8) * DMODEL + d0 + tx];
    __syncthreads();
    size_t ob = (size_t)b * DMODEL * QBEF;
#pragma unroll
    for (int i = 0; i < 4; i++) {
        float v = tile[tx][ty + i * 8];
        __nv_bfloat16 h = __float2bfloat16_rn(v);
        float hf = __bfloat162float(h);
        size_t o = ob + (size_t)(d0 + ty + i * 8) * QBEF + qb0 + tx;
        th[o] = h;
        tq[o] = to_fp8(hf);
        tr[o] = to_fp8((v - hf) * RSCALE);
    }
}

// ---------------------------------------------------------------------------
// Row softmax -> triple P
// ---------------------------------------------------------------------------
__global__ __launch_bounds__(256)
void softmax_kernel(const float* __restrict__ S,
                    __nv_bfloat16* __restrict__ Ph, unsigned char* __restrict__ Pq,
                    unsigned char* __restrict__ Pr)
{
    const float* p = S + (long long)blockIdx.x * NKEYS;
    const long long ob = (long long)blockIdx.x * NKEYS;
    const int tid = threadIdx.x;

    float v[16];
    float m = __int_as_float(0xff800000);
#pragma unroll
    for (int i = 0; i < 16; i++) { v[i] = p[tid + i * 256]; m = fmaxf(m, v[i]); }

    __shared__ float red[256];
    red[tid] = m; __syncthreads();
#pragma unroll
    for (int s = 128; s > 0; s >>= 1) {
        if (tid < s) red[tid] = fmaxf(red[tid], red[tid + s]);
        __syncthreads();
    }
    m = red[0]; __syncthreads();

    float sum = 0.0f;
#pragma unroll
    for (int i = 0; i < 16; i++) { v[i] = __expf(v[i] - m); sum += v[i]; }
    red[tid] = sum; __syncthreads();
#pragma unroll
    for (int s = 128; s > 0; s >>= 1) {
        if (tid < s) red[tid] += red[tid + s];
        __syncthreads();
    }
    const float inv = 1.0f / red[0];
#pragma unroll
    for (int i = 0; i < 16; i++) {
        float pv = v[i] * inv;
        __nv_bfloat16 h = __float2bfloat16_rn(pv);
        float hf = __bfloat162float(h);
        long long o = ob + tid + i * 256;
        Ph[o] = h;
        Pq[o] = to_fp8(hf);
        Pr[o] = to_fp8((pv - hf) * RSCALE);
    }
}

// ---------------------------------------------------------------------------
// Host
// ---------------------------------------------------------------------------
#define SYM(p, s) cudaGetSymbolAddress((void**)&p, s)

extern "C" void kernel_launch(void* const* d_in, const int* in_sizes, int n_in,
                              void* d_out, int out_size)
{
    (void)in_sizes; (void)n_in; (void)out_size;

    const float* queries = (const float*)d_in[0];
    const float* keys    = (const float*)d_in[1];
    const float* values  = (const float*)d_in[2];
    const int*   mask    = (const int*)d_in[3];
    const float* Wq = (const float*)d_in[4];
    const float* bq = (const float*)d_in[5];
    const float* Wk = (const float*)d_in[6];
    const float* bk = (const float*)d_in[7];
    const float* Wv = (const float*)d_in[8];
    const float* bv = (const float*)d_in[9];
    const float* Wo = (const float*)d_in[10];
    const float* bo = (const float*)d_in[11];
    const float* Wd = (const float*)d_in[12];
    const float* bd = (const float*)d_in[13];
    float* out = (float*)d_out;

    cudaFuncSetAttribute(gemm_h<0>, cudaFuncAttributeMaxDynamicSharedMemorySize, SMEM_G);
    cudaFuncSetAttribute(gemm_h<1>, cudaFuncAttributeMaxDynamicSharedMemorySize, SMEM_G);
    cudaFuncSetAttribute(gemm_h<2>, cudaFuncAttributeMaxDynamicSharedMemorySize, SMEM_G);

    __nv_bfloat16 *qTh,*knh,*vnh,*wdh,*wqh,*wkh,*wvh,*woh,*dsh,*qh,*kh,*vth,*ph,*ath;
    unsigned char *qTq,*qTr,*knq,*knr,*vnq,*vnr,*wdq,*wdr,*wqq,*wqr,*wkq,*wkr,*wvq,*wvr,*woq,*wor;
    unsigned char *dsq,*dsr,*qq,*qr,*kq,*kr,*vtq,*vtr,*pq,*pr,*atq,*atr;
    float* sS;
    SYM(qTh,g_qTh); SYM(qTq,g_qTq); SYM(qTr,g_qTr);
    SYM(knh,g_knh); SYM(knq,g_knq); SYM(knr,g_knr);
    SYM(vnh,g_vnh); SYM(vnq,g_vnq); SYM(vnr,g_vnr);
    SYM(wdh,g_wdh); SYM(wdq,g_wdq); SYM(wdr,g_wdr);
    SYM(wqh,g_wqh); SYM(wqq,g_wqq); SYM(wqr,g_wqr);
    SYM(wkh,g_wkh); SYM(wkq,g_wkq); SYM(wkr,g_wkr);
    SYM(wvh,g_wvh); SYM(wvq,g_wvq); SYM(wvr,g_wvr);
    SYM(woh,g_woh); SYM(woq,g_woq); SYM(wor,g_wor);
    SYM(dsh,g_dsh); SYM(dsq,g_dsq); SYM(dsr,g_dsr);
    SYM(qh,g_qh);   SYM(qq,g_qq);   SYM(qr,g_qr);
    SYM(kh,g_kh);   SYM(kq,g_kq);   SYM(kr,g_kr);
    SYM(vth,g_vth); SYM(vtq,g_vtq); SYM(vtr,g_vtr);
    SYM(ph,g_ph);   SYM(pq,g_pq);   SYM(pr,g_pr);
    SYM(ath,g_ath); SYM(atq,g_atq); SYM(atr,g_atr);
    SYM(sS,g_s);

    // prep
    tsplit_kernel<<<dim3(QBEF / 32, DMODEL / 32, BATCH), 256>>>(queries, qTh, qTq, qTr);
    split2_kernel<<<dim3((N_QKV / 4 + 255) / 256, 2), 256>>>(keys, values,
        knh, knq, knr, vnh, vnq, vnr);
    splitW_kernel<<<dim3((N_WD / 4 + 255) / 256, 5), 256>>>(Wd, Wq, Wk, Wv, Wo,
        wdh, wdq, wdr, wqh, wqq, wqr, wkh, wkq, wkr, wvh, wvq, wvr, woh, woq, wor);

    // 1. Downsample (NT): qds[b] = Wd @ qT[b]^T + bd(rows)
    gemm_h<1><<<dim3(DMODEL / 64, QAFT / 128, BATCH), 256, SMEM_G>>>(
        wdh, wdq, wdr, qTh, qTq, qTr, nullptr, dsh, dsq, dsr,
        QAFT, DMODEL, QBEF, 0, (long long)DMODEL * QBEF, (long long)QAFT * DMODEL,
        nullptr, bd, 1.0f, nullptr, 0, 0);

    // 2. Q projection: q = qds @ Wq^T + bq (flat batch)
    gemm_h<1><<<dim3(DMODEL / 64, BATCH * QAFT / 128, 1), 256, SMEM_G>>>(
        dsh, dsq, dsr, wqh, wqq, wqr, nullptr, qh, qq, qr,
        BATCH * QAFT, DMODEL, DMODEL, 0, 0, 0, bq, nullptr, 1.0f, nullptr, 0, 0);

    // 3. K projection
    gemm_h<1><<<dim3(DMODEL / 64, BATCH * NKEYS / 128, 1), 256, SMEM_G>>>(
        knh, knq, knr, wkh, wkq, wkr, nullptr, kh, kq, kr,
        BATCH * NKEYS, DMODEL, DMODEL, 0, 0, 0, bk, nullptr, 1.0f, nullptr, 0, 0);

    // 4. V projection -> transposed vT[b][d][nk]
    gemm_h<2><<<dim3(DMODEL / 64, NKEYS / 128, BATCH), 256, SMEM_G>>>(
        vnh, vnq, vnr, wvh, wvq, wvr, nullptr, vth, vtq, vtr,
        NKEYS, DMODEL, DMODEL,
        (long long)NKEYS * DMODEL, 0, (long long)DMODEL * NKEYS,
        bv, nullptr, 1.0f, nullptr, 0, NKEYS);

    // 5. Scores (NT): s = (q @ k^T)/sqrt(512), mask -> -inf
    gemm_h<0><<<dim3(NKEYS / 64, QAFT / 128, BATCH), 256, SMEM_G>>>(
        qh, qq, qr, kh, kq, kr, sS, nullptr, nullptr, nullptr,
        QAFT, NKEYS, DMODEL,
        (long long)QAFT * DMODEL, (long long)NKEYS * DMODEL, (long long)QAFT * NKEYS,
        nullptr, nullptr, 0.044194173824159216f, mask, (long long)QAFT * NKEYS, 0);

    // 6. Softmax -> triple P
    softmax_kernel<<<BATCH * QAFT, 256>>>(sS, ph, pq, pr);

    // 7. PV (NT vs vT): att[b] = P[b] @ vT[b]^T
    gemm_h<1><<<dim3(DMODEL / 64, QAFT / 128, BATCH), 256, SMEM_G>>>(
        ph, pq, pr, vth, vtq, vtr, nullptr, ath, atq, atr,
        QAFT, DMODEL, NKEYS,
        (long long)QAFT * NKEYS, (long long)DMODEL * NKEYS, (long long)QAFT * DMODEL,
        nullptr, nullptr, 1.0f, nullptr, 0, 0);

    // 8. Output projection -> fp32 d_out
    gemm_h<0><<<dim3(DMODEL / 64, BATCH * QAFT / 128, 1), 256, SMEM_G>>>(
        ath, atq, atr, woh, woq, wor, out, nullptr, nullptr, nullptr,
        BATCH * QAFT, DMODEL, DMODEL, 0, 0, 0, bo, nullptr, 1.0f, nullptr, 0, 0);
}